// round 13
// baseline (speedup 1.0000x reference)
#include <cuda_runtime.h>
#include <math.h>
#include <stdint.h>

#define N_E    8192
#define E_DIM  32
#define T_TOK  32768
#define ROW_B  48             // int8 row stride (conflict-free, 16B aligned)
#define NCHUNK 128            // codes per chunk per warp-group
#define CHUNKS 32             // 4096 codes per group / 128
#define MCTA   64
#define GRID_MAIN 512
#define WINDOW_I 800
#define CAND_CAP 32           // 8 producer threads x 4 entries -> overflow impossible
#define NEG_I  (-2147483647-1)

// ---- device scratch ----
__device__ float  g_en  [N_E * E_DIM];
__device__ float  g_bias[N_E];
__device__ char   g_Bq  [N_E * 32];
__device__ float  g_part[GRID_MAIN];
__device__ unsigned int g_done = 0;

// ---- smem layout (bytes) ----
#define A_OFF    0                      // 64 x 48 = 3072
#define B_OFF    3072                   // 4 buffers x 6144 = 24576 -> ends 27648
#define BUF_SZ   6144
#define CNT_OFF  27648                  // 64 ints -> 27904
#define LIST_OFF 27904                  // 64 x 32 ints = 8192 -> 36096
#define SMAX_OFF 36096                  // 128 ints -> 36608
#define SMEM_TOTAL 36608

#define CP_ASYNC16(s, g) asm volatile("cp.async.cg.shared.global [%0], [%1], 16;" :: "r"(s), "l"(g) : "memory")
#define CP_COMMIT()      asm volatile("cp.async.commit_group;" ::: "memory")
#define CP_WAIT1()       asm volatile("cp.async.wait_group 1;" ::: "memory")
#define CP_WAIT0()       asm volatile("cp.async.wait_group 0;" ::: "memory")

#define LDSM_X4(r0, r1, r2, r3, a)                                              \
    asm volatile("ldmatrix.sync.aligned.m8n8.x4.shared.b16 "                    \
                 "{%0,%1,%2,%3}, [%4];"                                         \
                 : "=r"(r0), "=r"(r1), "=r"(r2), "=r"(r3) : "r"(a))

__device__ __forceinline__ uint32_t smem_u32(const void* p) {
    uint32_t a;
    asm("{ .reg .u64 t; cvta.to.shared.u64 t, %1; cvt.u32.u64 %0, t; }" : "=r"(a) : "l"(p));
    return a;
}

__device__ __forceinline__ void imma(int& c0, int& c1, int& c2, int& c3,
                                     uint32_t a0, uint32_t a1, uint32_t a2, uint32_t a3,
                                     uint32_t b0, uint32_t b1) {
    asm volatile("mma.sync.aligned.m16n8k32.row.col.s32.s8.s8.s32 "
                 "{%0,%1,%2,%3}, {%4,%5,%6,%7}, {%8,%9}, {%0,%1,%2,%3};"
                 : "+r"(c0), "+r"(c1), "+r"(c2), "+r"(c3)
                 : "r"(a0), "r"(a1), "r"(a2), "r"(a3), "r"(b0), "r"(b1));
}

// rare-path int top-4 insertion (validated rounds 8-11)
#define INS4(s, n, b1, i1, b2, i2, b3, i3, b4, i4)                             \
    do { int _s = (s); int _n = (n);                                           \
         if (_s > (b4)) {                                                      \
             if (_s > (b2)) {                                                  \
                 if (_s > (b1)) { (b4)=(b3);(i4)=(i3); (b3)=(b2);(i3)=(i2);    \
                                  (b2)=(b1);(i2)=(i1); (b1)=_s;(i1)=_n; }      \
                 else { (b4)=(b3);(i4)=(i3); (b3)=(b2);(i3)=(i2); (b2)=_s;(i2)=_n; } \
             } else {                                                          \
                 if (_s > (b3)) { (b4)=(b3);(i4)=(i3); (b3)=_s;(i3)=_n; }      \
                 else { (b4)=_s;(i4)=_n; }                                     \
             }                                                                 \
         } } while (0)

// =====================================================================
// Prep (unchanged, validated)
// =====================================================================
__global__ void prep_kernel(const float* __restrict__ emb) {
    int row  = blockIdx.x * 8 + (threadIdx.x >> 5);
    int lane = threadIdx.x & 31;
    float v  = emb[row * E_DIM + lane];
    float ss = v * v;
    #pragma unroll
    for (int o = 16; o; o >>= 1) ss += __shfl_xor_sync(0xFFFFFFFFu, ss, o);
    float inv = 1.0f / fmaxf(sqrtf(ss), 1e-12f);
    float e = v * inv;
    g_en[row * E_DIM + lane] = e;
    float s2 = e * e;
    #pragma unroll
    for (int o = 16; o; o >>= 1) s2 += __shfl_xor_sync(0xFFFFFFFFu, s2, o);
    if (lane == 0) g_bias[row] = -0.5f * s2;
    g_Bq[row * 32 + lane] = (char)__float2int_rn(e * 127.0f);
}

// =====================================================================
// Main: 2 warp-groups x 4 warps; group g scans codes [g*4096,(g+1)*4096)
// with the round-10 validated per-thread top-4 loop. Merge via global
// max exchange, thr = max - 800, append top-4 >= thr (cap-proof).
// =====================================================================
__device__ __forceinline__ void prefetch_g(int grp, int ch, uint32_t bbase, int gtid) {
    const char* src = g_Bq + (size_t)(grp * 4096 + ch * NCHUNK + gtid) * 32;
    uint32_t dst = bbase + gtid * ROW_B;
    CP_ASYNC16(dst,      src);
    CP_ASYNC16(dst + 16, src + 16);
}

#define APPEND(tok, idx) do {                                                  \
    int _p = atomicAdd(&s_cnt[tok], 1);                                        \
    if (_p < CAND_CAP) s_list[(tok) * CAND_CAP + _p] = (idx); } while (0)

__global__ void __launch_bounds__(256, 4) vq_main_kernel(const float* __restrict__ z,
                                                         float* __restrict__ out) {
    extern __shared__ char smem[];
    const uint32_t sb = smem_u32(smem);
    const int tid  = threadIdx.x;
    const int grp  = tid >> 7;
    const int gtid = tid & 127;
    const int lane = tid & 31;
    const int w4   = gtid >> 5;
    const int g    = lane >> 2;
    const int tig  = lane & 3;
    const int tok0 = blockIdx.x * MCTA;
    const int tokA = w4 * 16 + g;
    const int tokB = tokA + 8;

    const uint32_t bb0 = sb + B_OFF + (uint32_t)(grp * 2) * BUF_SZ;
    const uint32_t bb1 = bb0 + BUF_SZ;

    prefetch_g(grp, 0, bb0, gtid); CP_COMMIT();
    prefetch_g(grp, 1, bb1, gtid); CP_COMMIT();

    // build int8 A tile (threads 0-63): one token per thread (validated)
    if (tid < MCTA) {
        const int t = tok0 + tid;
        float x[E_DIM];
        const float4* zr = (const float4*)(z + (size_t)t * E_DIM);
        float ss = 0.0f;
        #pragma unroll
        for (int j = 0; j < 8; j++) {
            float4 v = zr[j];
            x[4*j+0] = v.x; x[4*j+1] = v.y; x[4*j+2] = v.z; x[4*j+3] = v.w;
            ss += v.x*v.x + v.y*v.y + v.z*v.z + v.w*v.w;
        }
        float inv = 1.0f / fmaxf(sqrtf(ss), 1e-12f);
        char* arow = smem + A_OFF + tid * ROW_B;
        #pragma unroll
        for (int d = 0; d < E_DIM; d++)
            arow[d] = (char)__float2int_rn(x[d] * inv * 127.0f);
    }
    __syncthreads();

    // A fragments (validated round 10)
    uint32_t af0, af1, af2, af3;
    {
        const char* ab = smem + A_OFF;
        const int r0 = w4 * 16 + g;
        af0 = *(const uint32_t*)(ab + r0 * ROW_B + 4 * tig);
        af1 = *(const uint32_t*)(ab + (r0 + 8) * ROW_B + 4 * tig);
        af2 = *(const uint32_t*)(ab + r0 * ROW_B + 16 + 4 * tig);
        af3 = *(const uint32_t*)(ab + (r0 + 8) * ROW_B + 16 + 4 * tig);
    }

    int b1A = NEG_I, b2A = NEG_I, b3A = NEG_I, b4A = NEG_I;
    int b1B = NEG_I, b2B = NEG_I, b3B = NEG_I, b4B = NEG_I;
    int i1A = 0, i2A = 0, i3A = 0, i4A = 0;
    int i1B = 0, i2B = 0, i3B = 0, i4B = 0;

    // ldmatrix address map (validated round 10)
    const uint32_t lmo = (uint32_t)(lane & 7) * ROW_B
                       + (uint32_t)((lane >> 3) & 1) * 16
                       + (uint32_t)(lane >> 4) * (8 * ROW_B);

    for (int ch = 0; ch < CHUNKS; ch++) {
        CP_WAIT1();
        __syncthreads();
        const uint32_t bbase = (ch & 1) ? bb1 : bb0;
        const int nbase = grp * 4096 + ch * NCHUNK;

        #pragma unroll 4
        for (int np = 0; np < 8; np++) {             // 16 codes per iteration (round-10 granularity)
            uint32_t q0, q1, q2, q3;
            LDSM_X4(q0, q1, q2, q3, bbase + (uint32_t)np * (16 * ROW_B) + lmo);
            int c0 = 0, c1 = 0, c2 = 0, c3 = 0;
            int d0 = 0, d1 = 0, d2 = 0, d3 = 0;
            imma(c0, c1, c2, c3, af0, af1, af2, af3, q0, q1);   // codes +0..7
            imma(d0, d1, d2, d3, af0, af1, af2, af3, q2, q3);   // codes +8..15

            const int nb0 = nbase + np * 16 + 2 * tig;
            {
                int m4 = max(max(c0, c1), max(d0, d1));
                if (m4 > b4A) {
                    INS4(c0, nb0,     b1A, i1A, b2A, i2A, b3A, i3A, b4A, i4A);
                    INS4(c1, nb0 + 1, b1A, i1A, b2A, i2A, b3A, i3A, b4A, i4A);
                    INS4(d0, nb0 + 8, b1A, i1A, b2A, i2A, b3A, i3A, b4A, i4A);
                    INS4(d1, nb0 + 9, b1A, i1A, b2A, i2A, b3A, i3A, b4A, i4A);
                }
            }
            {
                int m4 = max(max(c2, c3), max(d2, d3));
                if (m4 > b4B) {
                    INS4(c2, nb0,     b1B, i1B, b2B, i2B, b3B, i3B, b4B, i4B);
                    INS4(c3, nb0 + 1, b1B, i1B, b2B, i2B, b3B, i3B, b4B, i4B);
                    INS4(d2, nb0 + 8, b1B, i1B, b2B, i2B, b3B, i3B, b4B, i4B);
                    INS4(d3, nb0 + 9, b1B, i1B, b2B, i2B, b3B, i3B, b4B, i4B);
                }
            }
        }
        __syncthreads();
        if (ch + 2 < CHUNKS) prefetch_g(grp, ch + 2, (ch & 1) ? bb1 : bb0, gtid);
        CP_COMMIT();
    }
    CP_WAIT0();

    // ---- merge: global max exchange, then threshold append ----
    int* s_cnt  = (int*)(smem + CNT_OFF);
    int* s_list = (int*)(smem + LIST_OFF);
    int* s_max  = (int*)(smem + SMAX_OFF);

    int mA = b1A, mB = b1B;
    #pragma unroll
    for (int o = 1; o <= 2; o <<= 1) {
        mA = max(mA, __shfl_xor_sync(0xFFFFFFFFu, mA, o));
        mB = max(mB, __shfl_xor_sync(0xFFFFFFFFu, mB, o));
    }
    if (tig == 0) {
        s_max[grp * 64 + tokA] = mA;
        s_max[grp * 64 + tokB] = mB;
    }
    if (tid < MCTA) s_cnt[tid] = 0;
    __syncthreads();

    const int thrA = max(s_max[tokA], s_max[64 + tokA]) - WINDOW_I;
    const int thrB = max(s_max[tokB], s_max[64 + tokB]) - WINDOW_I;
    if (b1A >= thrA) APPEND(tokA, i1A);
    if (b2A >= thrA) APPEND(tokA, i2A);
    if (b3A >= thrA) APPEND(tokA, i3A);
    if (b4A >= thrA) APPEND(tokA, i4A);
    if (b1B >= thrB) APPEND(tokB, i1B);
    if (b2B >= thrB) APPEND(tokB, i2B);
    if (b3B >= thrB) APPEND(tokB, i3B);
    if (b4B >= thrB) APPEND(tokB, i4B);
    __syncthreads();

    // ---- stage B: fp32 rescore + outputs + loss (validated path) ----
    float lsum = 0.0f;
    if (tid < MCTA) {
        const int t = tok0 + tid;
        float zn[E_DIM];
        const float4* zr = (const float4*)(z + (size_t)t * E_DIM);
        float ss = 0.0f;
        #pragma unroll
        for (int j = 0; j < 8; j++) {
            float4 v = zr[j];
            zn[4*j+0] = v.x; zn[4*j+1] = v.y; zn[4*j+2] = v.z; zn[4*j+3] = v.w;
            ss += v.x*v.x + v.y*v.y + v.z*v.z + v.w*v.w;
        }
        float inv = 1.0f / fmaxf(sqrtf(ss), 1e-12f);
        #pragma unroll
        for (int d = 0; d < E_DIM; d++) zn[d] *= inv;

        int nc = s_cnt[tid]; if (nc > CAND_CAP) nc = CAND_CAP;
        float best = -3.4e38f;
        int   bi   = 0x7FFFFFFF;
        for (int j = 0; j < nc; j++) {
            int ci = s_list[tid * CAND_CAP + j];
            const float* er = g_en + (size_t)ci * E_DIM;
            float dot = 0.0f;
            #pragma unroll
            for (int d = 0; d < E_DIM; d++) dot = fmaf(zn[d], er[d], dot);
            float s = dot + g_bias[ci];
            if (s > best || (s == best && ci < bi)) { best = s; bi = ci; }
        }

        float o[E_DIM];
        const float* eq = g_en + (size_t)bi * E_DIM;
        #pragma unroll
        for (int d = 0; d < E_DIM; d++) {
            float df = eq[d] - zn[d];
            lsum += df * df;
            o[d] = zn[d] + df;
        }
        float4* orow = (float4*)(out + (size_t)t * E_DIM);
        #pragma unroll
        for (int j = 0; j < 8; j++)
            orow[j] = make_float4(o[4*j], o[4*j+1], o[4*j+2], o[4*j+3]);
        out[(size_t)T_TOK * E_DIM + 1 + t] = (float)bi;
    }

    __syncthreads();
    float* s_red = (float*)smem;
    s_red[tid] = lsum;
    __syncthreads();
    #pragma unroll
    for (int k = 128; k; k >>= 1) {
        if (tid < k) s_red[tid] += s_red[tid + k];
        __syncthreads();
    }
    __shared__ unsigned int s_last;
    if (tid == 0) {
        g_part[blockIdx.x] = s_red[0];
        __threadfence();
        s_last = atomicAdd(&g_done, 1u);
    }
    __syncthreads();

    if (s_last == GRID_MAIN - 1) {
        s_red[tid] = g_part[tid] + g_part[tid + 256];
        __syncthreads();
        #pragma unroll
        for (int k = 128; k; k >>= 1) {
            if (tid < k) s_red[tid] += s_red[tid + k];
            __syncthreads();
        }
        if (tid == 0) {
            out[(size_t)T_TOK * E_DIM] = 1.25f * s_red[0] / (float)(T_TOK * E_DIM);
            g_done = 0;
        }
    }
}

extern "C" void kernel_launch(void* const* d_in, const int* in_sizes, int n_in,
                              void* d_out, int out_size) {
    const float* z   = (const float*)d_in[0];
    const float* emb = (const float*)d_in[1];
    float* out = (float*)d_out;

    cudaFuncSetAttribute(vq_main_kernel, cudaFuncAttributeMaxDynamicSharedMemorySize, SMEM_TOTAL);

    prep_kernel<<<N_E / 8, 256>>>(emb);
    vq_main_kernel<<<GRID_MAIN, 256, SMEM_TOTAL>>>(z, out);
}

// round 16
// speedup vs baseline: 1.2315x; 1.2315x over previous
#include <cuda_runtime.h>
#include <math.h>
#include <stdint.h>

#define N_E    8192
#define E_DIM  32
#define T_TOK  32768
#define ROW_B  48             // int8 row stride (conflict-free, 16B aligned)
#define NCHUNK 128            // codes per chunk per warp-group
#define CHUNKS 32             // 4096 codes per group / 128
#define MCTA   64
#define GRID_MAIN 512
#define WINDOW_I 800
#define CAND_CAP 32           // 8 producer threads x 4 entries -> overflow impossible
#define NEG_I  (-2147483647-1)

// ---- device scratch ----
__device__ float  g_en  [N_E * E_DIM];
__device__ float  g_bias[N_E];
__device__ char   g_Bq  [N_E * 32];
__device__ float  g_part[GRID_MAIN];
__device__ unsigned int g_done = 0;

// ---- smem layout (bytes) ----
#define A_OFF    0                      // 64 x 48 = 3072
#define B_OFF    3072                   // 4 buffers x 6144 = 24576 -> 27648
#define BUF_SZ   6144
#define CNT_OFF  27648                  // 64 ints -> 27904
#define LIST_OFF 27904                  // 64 x 32 ints = 8192 -> 36096
#define SMAX_OFF 36096                  // 128 ints -> 36608
#define SMEM_TOTAL 36608

#define CP_ASYNC16(s, g) asm volatile("cp.async.cg.shared.global [%0], [%1], 16;" :: "r"(s), "l"(g) : "memory")
#define CP_COMMIT()      asm volatile("cp.async.commit_group;" ::: "memory")
#define CP_WAIT1()       asm volatile("cp.async.wait_group 1;" ::: "memory")
#define CP_WAIT0()       asm volatile("cp.async.wait_group 0;" ::: "memory")

#define LDSM_X4(r0, r1, r2, r3, a)                                              \
    asm volatile("ldmatrix.sync.aligned.m8n8.x4.shared.b16 "                    \
                 "{%0,%1,%2,%3}, [%4];"                                         \
                 : "=r"(r0), "=r"(r1), "=r"(r2), "=r"(r3) : "r"(a))

__device__ __forceinline__ uint32_t smem_u32(const void* p) {
    uint32_t a;
    asm("{ .reg .u64 t; cvta.to.shared.u64 t, %1; cvt.u32.u64 %0, t; }" : "=r"(a) : "l"(p));
    return a;
}

__device__ __forceinline__ void imma(int& c0, int& c1, int& c2, int& c3,
                                     uint32_t a0, uint32_t a1, uint32_t a2, uint32_t a3,
                                     uint32_t b0, uint32_t b1) {
    asm volatile("mma.sync.aligned.m16n8k32.row.col.s32.s8.s8.s32 "
                 "{%0,%1,%2,%3}, {%4,%5,%6,%7}, {%8,%9}, {%0,%1,%2,%3};"
                 : "+r"(c0), "+r"(c1), "+r"(c2), "+r"(c3)
                 : "r"(a0), "r"(a1), "r"(a2), "r"(a3), "r"(b0), "r"(b1));
}

// branch-free bubble insertion of packed value v into sorted t1>=t2>=t3>=t4
#define BINS(vexpr, t1, t2, t3, t4)                                            \
    do { int _v = (vexpr); int _n;                                             \
         _n = max(t1, _v); _v = min(t1, _v); t1 = _n;                          \
         _n = max(t2, _v); _v = min(t2, _v); t2 = _n;                          \
         _n = max(t3, _v); _v = min(t3, _v); t3 = _n;                          \
         t4 = max(t4, _v); } while (0)

// =====================================================================
// Prep (unchanged, validated)
// =====================================================================
__global__ void prep_kernel(const float* __restrict__ emb) {
    int row  = blockIdx.x * 8 + (threadIdx.x >> 5);
    int lane = threadIdx.x & 31;
    float v  = emb[row * E_DIM + lane];
    float ss = v * v;
    #pragma unroll
    for (int o = 16; o; o >>= 1) ss += __shfl_xor_sync(0xFFFFFFFFu, ss, o);
    float inv = 1.0f / fmaxf(sqrtf(ss), 1e-12f);
    float e = v * inv;
    g_en[row * E_DIM + lane] = e;
    float s2 = e * e;
    #pragma unroll
    for (int o = 16; o; o >>= 1) s2 += __shfl_xor_sync(0xFFFFFFFFu, s2, o);
    if (lane == 0) g_bias[row] = -0.5f * s2;
    g_Bq[row * 32 + lane] = (char)__float2int_rn(e * 127.0f);
}

// =====================================================================
// Main: 2 warp-groups x 4 warps; group g scans codes [g*4096,(g+1)*4096).
// Branch-free packed sorted top-4 per thread (1024-code subset, the
// twice-validated coverage class); window merge; fp32 rescore.
// =====================================================================
__device__ __forceinline__ void prefetch_g(int grp, int ch, uint32_t bbase, int gtid) {
    const char* src = g_Bq + (size_t)(grp * 4096 + ch * NCHUNK + gtid) * 32;
    uint32_t dst = bbase + gtid * ROW_B;
    CP_ASYNC16(dst,      src);
    CP_ASYNC16(dst + 16, src + 16);
}

#define APPEND(tok, idx) do {                                                  \
    int _p = atomicAdd(&s_cnt[tok], 1);                                        \
    if (_p < CAND_CAP) s_list[(tok) * CAND_CAP + _p] = (idx); } while (0)

__global__ void __launch_bounds__(256, 4) vq_main_kernel(const float* __restrict__ z,
                                                         float* __restrict__ out) {
    extern __shared__ char smem[];
    const uint32_t sb = smem_u32(smem);
    const int tid  = threadIdx.x;
    const int grp  = tid >> 7;
    const int gtid = tid & 127;
    const int lane = tid & 31;
    const int w4   = gtid >> 5;
    const int g    = lane >> 2;
    const int tig  = lane & 3;
    const int tok0 = blockIdx.x * MCTA;
    const int tokA = w4 * 16 + g;
    const int tokB = tokA + 8;

    const uint32_t bb0 = sb + B_OFF + (uint32_t)(grp * 2) * BUF_SZ;
    const uint32_t bb1 = bb0 + BUF_SZ;

    prefetch_g(grp, 0, bb0, gtid); CP_COMMIT();
    prefetch_g(grp, 1, bb1, gtid); CP_COMMIT();

    // build int8 A tile (threads 0-63): one token per thread (validated)
    if (tid < MCTA) {
        const int t = tok0 + tid;
        float x[E_DIM];
        const float4* zr = (const float4*)(z + (size_t)t * E_DIM);
        float ss = 0.0f;
        #pragma unroll
        for (int j = 0; j < 8; j++) {
            float4 v = zr[j];
            x[4*j+0] = v.x; x[4*j+1] = v.y; x[4*j+2] = v.z; x[4*j+3] = v.w;
            ss += v.x*v.x + v.y*v.y + v.z*v.z + v.w*v.w;
        }
        float inv = 1.0f / fmaxf(sqrtf(ss), 1e-12f);
        char* arow = smem + A_OFF + tid * ROW_B;
        #pragma unroll
        for (int d = 0; d < E_DIM; d++)
            arow[d] = (char)__float2int_rn(x[d] * inv * 127.0f);
    }
    __syncthreads();

    // A fragments (validated round 10)
    uint32_t af0, af1, af2, af3;
    {
        const char* ab = smem + A_OFF;
        const int r0 = w4 * 16 + g;
        af0 = *(const uint32_t*)(ab + r0 * ROW_B + 4 * tig);
        af1 = *(const uint32_t*)(ab + (r0 + 8) * ROW_B + 4 * tig);
        af2 = *(const uint32_t*)(ab + r0 * ROW_B + 16 + 4 * tig);
        af3 = *(const uint32_t*)(ab + (r0 + 8) * ROW_B + 16 + 4 * tig);
    }

    // packed (score<<13)+code sorted top-4 per token
    int t1A = NEG_I, t2A = NEG_I, t3A = NEG_I, t4A = NEG_I;
    int t1B = NEG_I, t2B = NEG_I, t3B = NEG_I, t4B = NEG_I;

    // ldmatrix address map (validated round 10)
    const uint32_t lmo = (uint32_t)(lane & 7) * ROW_B
                       + (uint32_t)((lane >> 3) & 1) * 16
                       + (uint32_t)(lane >> 4) * (8 * ROW_B);

    for (int ch = 0; ch < CHUNKS; ch++) {
        CP_WAIT1();
        __syncthreads();
        const uint32_t bbase = (ch & 1) ? bb1 : bb0;
        const int nbase = grp * 4096 + ch * NCHUNK + 2 * tig;

        #pragma unroll
        for (int np = 0; np < 8; np++) {             // 16 codes per iteration
            uint32_t q0, q1, q2, q3;
            LDSM_X4(q0, q1, q2, q3, bbase + (uint32_t)np * (16 * ROW_B) + lmo);
            int c0 = 0, c1 = 0, c2 = 0, c3 = 0;
            int d0 = 0, d1 = 0, d2 = 0, d3 = 0;
            imma(c0, c1, c2, c3, af0, af1, af2, af3, q0, q1);   // codes +0..7
            imma(d0, d1, d2, d3, af0, af1, af2, af3, q2, q3);   // codes +8..15

            const int nb0 = nbase + np * 16;
            // token A (row g): c0,c1 -> nb0,nb0+1 ; d0,d1 -> nb0+8,+9
            BINS((c0 << 13) + nb0,     t1A, t2A, t3A, t4A);
            BINS((c1 << 13) + nb0 + 1, t1A, t2A, t3A, t4A);
            BINS((d0 << 13) + nb0 + 8, t1A, t2A, t3A, t4A);
            BINS((d1 << 13) + nb0 + 9, t1A, t2A, t3A, t4A);
            // token B (row g+8): c2,c3,d2,d3
            BINS((c2 << 13) + nb0,     t1B, t2B, t3B, t4B);
            BINS((c3 << 13) + nb0 + 1, t1B, t2B, t3B, t4B);
            BINS((d2 << 13) + nb0 + 8, t1B, t2B, t3B, t4B);
            BINS((d3 << 13) + nb0 + 9, t1B, t2B, t3B, t4B);
        }
        __syncthreads();
        if (ch + 2 < CHUNKS) prefetch_g(grp, ch + 2, (ch & 1) ? bb1 : bb0, gtid);
        CP_COMMIT();
    }
    CP_WAIT0();

    // ---- merge: global packed-max exchange, then threshold append ----
    int* s_cnt  = (int*)(smem + CNT_OFF);
    int* s_list = (int*)(smem + LIST_OFF);
    int* s_max  = (int*)(smem + SMAX_OFF);

    int mA = t1A, mB = t1B;
    #pragma unroll
    for (int o = 1; o <= 2; o <<= 1) {
        mA = max(mA, __shfl_xor_sync(0xFFFFFFFFu, mA, o));
        mB = max(mB, __shfl_xor_sync(0xFFFFFFFFu, mB, o));
    }
    if (tig == 0) {
        s_max[grp * 64 + tokA] = mA;
        s_max[grp * 64 + tokB] = mB;
    }
    if (tid < MCTA) s_cnt[tid] = 0;
    __syncthreads();

    const int thrA = (max(s_max[tokA], s_max[64 + tokA]) >> 13) - WINDOW_I;
    const int thrB = (max(s_max[tokB], s_max[64 + tokB]) >> 13) - WINDOW_I;
    if ((t1A >> 13) >= thrA) APPEND(tokA, t1A & 8191);
    if ((t2A >> 13) >= thrA) APPEND(tokA, t2A & 8191);
    if ((t3A >> 13) >= thrA) APPEND(tokA, t3A & 8191);
    if ((t4A >> 13) >= thrA) APPEND(tokA, t4A & 8191);
    if ((t1B >> 13) >= thrB) APPEND(tokB, t1B & 8191);
    if ((t2B >> 13) >= thrB) APPEND(tokB, t2B & 8191);
    if ((t3B >> 13) >= thrB) APPEND(tokB, t3B & 8191);
    if ((t4B >> 13) >= thrB) APPEND(tokB, t4B & 8191);
    __syncthreads();

    // ---- stage B: fp32 rescore + outputs + loss (validated path) ----
    float lsum = 0.0f;
    if (tid < MCTA) {
        const int t = tok0 + tid;
        float zn[E_DIM];
        const float4* zr = (const float4*)(z + (size_t)t * E_DIM);
        float ss = 0.0f;
        #pragma unroll
        for (int j = 0; j < 8; j++) {
            float4 v = zr[j];
            zn[4*j+0] = v.x; zn[4*j+1] = v.y; zn[4*j+2] = v.z; zn[4*j+3] = v.w;
            ss += v.x*v.x + v.y*v.y + v.z*v.z + v.w*v.w;
        }
        float inv = 1.0f / fmaxf(sqrtf(ss), 1e-12f);
        #pragma unroll
        for (int d = 0; d < E_DIM; d++) zn[d] *= inv;

        int nc = s_cnt[tid]; if (nc > CAND_CAP) nc = CAND_CAP;
        float best = -3.4e38f;
        int   bi   = 0x7FFFFFFF;
        for (int j = 0; j < nc; j++) {
            int ci = s_list[tid * CAND_CAP + j];
            const float* er = g_en + (size_t)ci * E_DIM;
            float dot = 0.0f;
            #pragma unroll
            for (int d = 0; d < E_DIM; d++) dot = fmaf(zn[d], er[d], dot);
            float s = dot + g_bias[ci];
            if (s > best || (s == best && ci < bi)) { best = s; bi = ci; }
        }

        float o[E_DIM];
        const float* eq = g_en + (size_t)bi * E_DIM;
        #pragma unroll
        for (int d = 0; d < E_DIM; d++) {
            float df = eq[d] - zn[d];
            lsum += df * df;
            o[d] = zn[d] + df;
        }
        float4* orow = (float4*)(out + (size_t)t * E_DIM);
        #pragma unroll
        for (int j = 0; j < 8; j++)
            orow[j] = make_float4(o[4*j], o[4*j+1], o[4*j+2], o[4*j+3]);
        out[(size_t)T_TOK * E_DIM + 1 + t] = (float)bi;
    }

    __syncthreads();
    float* s_red = (float*)smem;
    s_red[tid] = lsum;
    __syncthreads();
    #pragma unroll
    for (int k = 128; k; k >>= 1) {
        if (tid < k) s_red[tid] += s_red[tid + k];
        __syncthreads();
    }
    __shared__ unsigned int s_last;
    if (tid == 0) {
        g_part[blockIdx.x] = s_red[0];
        __threadfence();
        s_last = atomicAdd(&g_done, 1u);
    }
    __syncthreads();

    if (s_last == GRID_MAIN - 1) {
        s_red[tid] = g_part[tid] + g_part[tid + 256];
        __syncthreads();
        #pragma unroll
        for (int k = 128; k; k >>= 1) {
            if (tid < k) s_red[tid] += s_red[tid + k];
            __syncthreads();
        }
        if (tid == 0) {
            out[(size_t)T_TOK * E_DIM] = 1.25f * s_red[0] / (float)(T_TOK * E_DIM);
            g_done = 0;
        }
    }
}

extern "C" void kernel_launch(void* const* d_in, const int* in_sizes, int n_in,
                              void* d_out, int out_size) {
    const float* z   = (const float*)d_in[0];
    const float* emb = (const float*)d_in[1];
    float* out = (float*)d_out;

    cudaFuncSetAttribute(vq_main_kernel, cudaFuncAttributeMaxDynamicSharedMemorySize, SMEM_TOTAL);

    prep_kernel<<<N_E / 8, 256>>>(emb);
    vq_main_kernel<<<GRID_MAIN, 256, SMEM_TOTAL>>>(z, out);
}

// round 17
// speedup vs baseline: 1.5326x; 1.2445x over previous
#include <cuda_runtime.h>
#include <math.h>
#include <stdint.h>

#define N_E    8192
#define E_DIM  32
#define T_TOK  32768
#define ROW_B  48             // int8 row stride (conflict-free, 16B aligned)
#define NCHUNK 128            // codes per chunk per warp-group
#define CHUNKS 32             // 4096 codes per group / 128
#define MCTA   64
#define GRID_MAIN 512
#define WINDOW_I 800
#define CAND_CAP 32           // 8 producer threads x 4 entries -> overflow impossible
#define NEG_I  (-2147483647-1)

// ---- device scratch ----
__device__ float  g_en  [N_E * E_DIM];
__device__ float  g_bias[N_E];
__device__ char   g_Bq  [N_E * 32];
__device__ float  g_part[GRID_MAIN];
__device__ unsigned int g_done = 0;

// ---- smem layout (bytes) ----
#define A_OFF    0                      // 64 x 48 = 3072
#define B_OFF    3072                   // 4 buffers x 6144 = 24576 -> 27648
#define BUF_SZ   6144
#define CNT_OFF  27648                  // 64 ints -> 27904
#define LIST_OFF 27904                  // 64 x 32 ints = 8192 -> 36096
#define SMAX_OFF 36096                  // 128 ints -> 36608
#define SMEM_TOTAL 36608

#define CP_ASYNC16(s, g) asm volatile("cp.async.cg.shared.global [%0], [%1], 16;" :: "r"(s), "l"(g) : "memory")
#define CP_COMMIT()      asm volatile("cp.async.commit_group;" ::: "memory")
#define CP_WAIT1()       asm volatile("cp.async.wait_group 1;" ::: "memory")
#define CP_WAIT0()       asm volatile("cp.async.wait_group 0;" ::: "memory")

#define LDSM_X4(r0, r1, r2, r3, a)                                              \
    asm volatile("ldmatrix.sync.aligned.m8n8.x4.shared.b16 "                    \
                 "{%0,%1,%2,%3}, [%4];"                                         \
                 : "=r"(r0), "=r"(r1), "=r"(r2), "=r"(r3) : "r"(a))

__device__ __forceinline__ uint32_t smem_u32(const void* p) {
    uint32_t a;
    asm("{ .reg .u64 t; cvta.to.shared.u64 t, %1; cvt.u32.u64 %0, t; }" : "=r"(a) : "l"(p));
    return a;
}

__device__ __forceinline__ void imma(int& c0, int& c1, int& c2, int& c3,
                                     uint32_t a0, uint32_t a1, uint32_t a2, uint32_t a3,
                                     uint32_t b0, uint32_t b1) {
    asm volatile("mma.sync.aligned.m16n8k32.row.col.s32.s8.s8.s32 "
                 "{%0,%1,%2,%3}, {%4,%5,%6,%7}, {%8,%9}, {%0,%1,%2,%3};"
                 : "+r"(c0), "+r"(c1), "+r"(c2), "+r"(c3)
                 : "r"(a0), "r"(a1), "r"(a2), "r"(a3), "r"(b0), "r"(b1));
}

// branch-free bubble insertion of packed value v into sorted t1>=t2>=t3>=t4
#define BINS(vexpr, t1, t2, t3, t4)                                            \
    do { int _v = (vexpr); int _n;                                             \
         _n = max(t1, _v); _v = min(t1, _v); t1 = _n;                          \
         _n = max(t2, _v); _v = min(t2, _v); t2 = _n;                          \
         _n = max(t3, _v); _v = min(t3, _v); t3 = _n;                          \
         t4 = max(t4, _v); } while (0)

// branch-free tournament: sorted top-2 (M >= S) of 8 packed values
#define TOP2_OF8(a0,a1,a2,a3,a4,a5,a6,a7, M, S)                                \
    do { int _h0 = max(a0,a1), _l0 = min(a0,a1);                               \
         int _h1 = max(a2,a3), _l1 = min(a2,a3);                               \
         int _h2 = max(a4,a5), _l2 = min(a4,a5);                               \
         int _h3 = max(a6,a7), _l3 = min(a6,a7);                               \
         int _m01 = max(_h0,_h1), _s01 = max(min(_h0,_h1), max(_l0,_l1));      \
         int _m23 = max(_h2,_h3), _s23 = max(min(_h2,_h3), max(_l2,_l3));      \
         M = max(_m01,_m23);                                                   \
         S = max(min(_m01,_m23), max(_s01,_s23)); } while (0)

// =====================================================================
// Prep (unchanged, validated)
// =====================================================================
__global__ void prep_kernel(const float* __restrict__ emb) {
    int row  = blockIdx.x * 8 + (threadIdx.x >> 5);
    int lane = threadIdx.x & 31;
    float v  = emb[row * E_DIM + lane];
    float ss = v * v;
    #pragma unroll
    for (int o = 16; o; o >>= 1) ss += __shfl_xor_sync(0xFFFFFFFFu, ss, o);
    float inv = 1.0f / fmaxf(sqrtf(ss), 1e-12f);
    float e = v * inv;
    g_en[row * E_DIM + lane] = e;
    float s2 = e * e;
    #pragma unroll
    for (int o = 16; o; o >>= 1) s2 += __shfl_xor_sync(0xFFFFFFFFu, s2, o);
    if (lane == 0) g_bias[row] = -0.5f * s2;
    g_Bq[row * 32 + lane] = (char)__float2int_rn(e * 127.0f);
}

// =====================================================================
// Main: 2 warp-groups x 4 warps; group g scans codes [g*4096,(g+1)*4096).
// 32 codes/iter; per token: branch-free top-2-of-8 tournament feeding a
// packed sorted top-4 (coverage class validated rounds 10/13/16).
// =====================================================================
__device__ __forceinline__ void prefetch_g(int grp, int ch, uint32_t bbase, int gtid) {
    const char* src = g_Bq + (size_t)(grp * 4096 + ch * NCHUNK + gtid) * 32;
    uint32_t dst = bbase + gtid * ROW_B;
    CP_ASYNC16(dst,      src);
    CP_ASYNC16(dst + 16, src + 16);
}

#define APPEND(tok, idx) do {                                                  \
    int _p = atomicAdd(&s_cnt[tok], 1);                                        \
    if (_p < CAND_CAP) s_list[(tok) * CAND_CAP + _p] = (idx); } while (0)

__global__ void __launch_bounds__(256, 3) vq_main_kernel(const float* __restrict__ z,
                                                         float* __restrict__ out) {
    extern __shared__ char smem[];
    const uint32_t sb = smem_u32(smem);
    const int tid  = threadIdx.x;
    const int grp  = tid >> 7;
    const int gtid = tid & 127;
    const int lane = tid & 31;
    const int w4   = gtid >> 5;
    const int g    = lane >> 2;
    const int tig  = lane & 3;
    const int tok0 = blockIdx.x * MCTA;
    const int tokA = w4 * 16 + g;
    const int tokB = tokA + 8;

    const uint32_t bb0 = sb + B_OFF + (uint32_t)(grp * 2) * BUF_SZ;
    const uint32_t bb1 = bb0 + BUF_SZ;

    prefetch_g(grp, 0, bb0, gtid); CP_COMMIT();
    prefetch_g(grp, 1, bb1, gtid); CP_COMMIT();

    // build int8 A tile (threads 0-63): one token per thread (validated)
    if (tid < MCTA) {
        const int t = tok0 + tid;
        float x[E_DIM];
        const float4* zr = (const float4*)(z + (size_t)t * E_DIM);
        float ss = 0.0f;
        #pragma unroll
        for (int j = 0; j < 8; j++) {
            float4 v = zr[j];
            x[4*j+0] = v.x; x[4*j+1] = v.y; x[4*j+2] = v.z; x[4*j+3] = v.w;
            ss += v.x*v.x + v.y*v.y + v.z*v.z + v.w*v.w;
        }
        float inv = 1.0f / fmaxf(sqrtf(ss), 1e-12f);
        char* arow = smem + A_OFF + tid * ROW_B;
        #pragma unroll
        for (int d = 0; d < E_DIM; d++)
            arow[d] = (char)__float2int_rn(x[d] * inv * 127.0f);
    }
    __syncthreads();

    // A fragments (validated round 10)
    uint32_t af0, af1, af2, af3;
    {
        const char* ab = smem + A_OFF;
        const int r0 = w4 * 16 + g;
        af0 = *(const uint32_t*)(ab + r0 * ROW_B + 4 * tig);
        af1 = *(const uint32_t*)(ab + (r0 + 8) * ROW_B + 4 * tig);
        af2 = *(const uint32_t*)(ab + r0 * ROW_B + 16 + 4 * tig);
        af3 = *(const uint32_t*)(ab + (r0 + 8) * ROW_B + 16 + 4 * tig);
    }

    // packed (score<<13)+code sorted top-4 per token
    int t1A = NEG_I, t2A = NEG_I, t3A = NEG_I, t4A = NEG_I;
    int t1B = NEG_I, t2B = NEG_I, t3B = NEG_I, t4B = NEG_I;

    // ldmatrix address map (validated round 10)
    const uint32_t lmo = (uint32_t)(lane & 7) * ROW_B
                       + (uint32_t)((lane >> 3) & 1) * 16
                       + (uint32_t)(lane >> 4) * (8 * ROW_B);

    for (int ch = 0; ch < CHUNKS; ch++) {
        CP_WAIT1();
        __syncthreads();
        const uint32_t bbase = (ch & 1) ? bb1 : bb0;
        const int nbase = grp * 4096 + ch * NCHUNK + 2 * tig;

        #pragma unroll
        for (int np2 = 0; np2 < 4; np2++) {          // 32 codes per iteration
            uint32_t q0, q1, q2, q3, p0, p1, p2, p3;
            uint32_t a0 = bbase + (uint32_t)np2 * (32 * ROW_B) + lmo;
            LDSM_X4(q0, q1, q2, q3, a0);
            LDSM_X4(p0, p1, p2, p3, a0 + 16 * ROW_B);
            int c0=0,c1=0,c2=0,c3=0, d0=0,d1=0,d2=0,d3=0;
            int e0=0,e1=0,e2=0,e3=0, f0=0,f1=0,f2=0,f3=0;
            imma(c0, c1, c2, c3, af0, af1, af2, af3, q0, q1);   // codes +0..7
            imma(d0, d1, d2, d3, af0, af1, af2, af3, q2, q3);   // codes +8..15
            imma(e0, e1, e2, e3, af0, af1, af2, af3, p0, p1);   // codes +16..23
            imma(f0, f1, f2, f3, af0, af1, af2, af3, p2, p3);   // codes +24..31

            const int nb0 = nbase + np2 * 32;
            // token A (row g)
            {
                int MA, SA;
                TOP2_OF8((c0 << 13) + nb0,      (c1 << 13) + nb0 + 1,
                         (d0 << 13) + nb0 + 8,  (d1 << 13) + nb0 + 9,
                         (e0 << 13) + nb0 + 16, (e1 << 13) + nb0 + 17,
                         (f0 << 13) + nb0 + 24, (f1 << 13) + nb0 + 25, MA, SA);
                BINS(MA, t1A, t2A, t3A, t4A);
                BINS(SA, t1A, t2A, t3A, t4A);
            }
            // token B (row g+8)
            {
                int MB, SB;
                TOP2_OF8((c2 << 13) + nb0,      (c3 << 13) + nb0 + 1,
                         (d2 << 13) + nb0 + 8,  (d3 << 13) + nb0 + 9,
                         (e2 << 13) + nb0 + 16, (e3 << 13) + nb0 + 17,
                         (f2 << 13) + nb0 + 24, (f3 << 13) + nb0 + 25, MB, SB);
                BINS(MB, t1B, t2B, t3B, t4B);
                BINS(SB, t1B, t2B, t3B, t4B);
            }
        }
        __syncthreads();
        if (ch + 2 < CHUNKS) prefetch_g(grp, ch + 2, (ch & 1) ? bb1 : bb0, gtid);
        CP_COMMIT();
    }
    CP_WAIT0();

    // ---- merge: global packed-max exchange, then threshold append ----
    int* s_cnt  = (int*)(smem + CNT_OFF);
    int* s_list = (int*)(smem + LIST_OFF);
    int* s_max  = (int*)(smem + SMAX_OFF);

    int mA = t1A, mB = t1B;
    #pragma unroll
    for (int o = 1; o <= 2; o <<= 1) {
        mA = max(mA, __shfl_xor_sync(0xFFFFFFFFu, mA, o));
        mB = max(mB, __shfl_xor_sync(0xFFFFFFFFu, mB, o));
    }
    if (tig == 0) {
        s_max[grp * 64 + tokA] = mA;
        s_max[grp * 64 + tokB] = mB;
    }
    if (tid < MCTA) s_cnt[tid] = 0;
    __syncthreads();

    const int thrA = (max(s_max[tokA], s_max[64 + tokA]) >> 13) - WINDOW_I;
    const int thrB = (max(s_max[tokB], s_max[64 + tokB]) >> 13) - WINDOW_I;
    if ((t1A >> 13) >= thrA) APPEND(tokA, t1A & 8191);
    if ((t2A >> 13) >= thrA) APPEND(tokA, t2A & 8191);
    if ((t3A >> 13) >= thrA) APPEND(tokA, t3A & 8191);
    if ((t4A >> 13) >= thrA) APPEND(tokA, t4A & 8191);
    if ((t1B >> 13) >= thrB) APPEND(tokB, t1B & 8191);
    if ((t2B >> 13) >= thrB) APPEND(tokB, t2B & 8191);
    if ((t3B >> 13) >= thrB) APPEND(tokB, t3B & 8191);
    if ((t4B >> 13) >= thrB) APPEND(tokB, t4B & 8191);
    __syncthreads();

    // ---- stage B: fp32 rescore + outputs + loss (validated path) ----
    float lsum = 0.0f;
    if (tid < MCTA) {
        const int t = tok0 + tid;
        float zn[E_DIM];
        const float4* zr = (const float4*)(z + (size_t)t * E_DIM);
        float ss = 0.0f;
        #pragma unroll
        for (int j = 0; j < 8; j++) {
            float4 v = zr[j];
            zn[4*j+0] = v.x; zn[4*j+1] = v.y; zn[4*j+2] = v.z; zn[4*j+3] = v.w;
            ss += v.x*v.x + v.y*v.y + v.z*v.z + v.w*v.w;
        }
        float inv = 1.0f / fmaxf(sqrtf(ss), 1e-12f);
        #pragma unroll
        for (int d = 0; d < E_DIM; d++) zn[d] *= inv;

        int nc = s_cnt[tid]; if (nc > CAND_CAP) nc = CAND_CAP;
        float best = -3.4e38f;
        int   bi   = 0x7FFFFFFF;
        for (int j = 0; j < nc; j++) {
            int ci = s_list[tid * CAND_CAP + j];
            const float* er = g_en + (size_t)ci * E_DIM;
            float dot = 0.0f;
            #pragma unroll
            for (int d = 0; d < E_DIM; d++) dot = fmaf(zn[d], er[d], dot);
            float s = dot + g_bias[ci];
            if (s > best || (s == best && ci < bi)) { best = s; bi = ci; }
        }

        float o[E_DIM];
        const float* eq = g_en + (size_t)bi * E_DIM;
        #pragma unroll
        for (int d = 0; d < E_DIM; d++) {
            float df = eq[d] - zn[d];
            lsum += df * df;
            o[d] = zn[d] + df;
        }
        float4* orow = (float4*)(out + (size_t)t * E_DIM);
        #pragma unroll
        for (int j = 0; j < 8; j++)
            orow[j] = make_float4(o[4*j], o[4*j+1], o[4*j+2], o[4*j+3]);
        out[(size_t)T_TOK * E_DIM + 1 + t] = (float)bi;
    }

    __syncthreads();
    float* s_red = (float*)smem;
    s_red[tid] = lsum;
    __syncthreads();
    #pragma unroll
    for (int k = 128; k; k >>= 1) {
        if (tid < k) s_red[tid] += s_red[tid + k];
        __syncthreads();
    }
    __shared__ unsigned int s_last;
    if (tid == 0) {
        g_part[blockIdx.x] = s_red[0];
        __threadfence();
        s_last = atomicAdd(&g_done, 1u);
    }
    __syncthreads();

    if (s_last == GRID_MAIN - 1) {
        s_red[tid] = g_part[tid] + g_part[tid + 256];
        __syncthreads();
        #pragma unroll
        for (int k = 128; k; k >>= 1) {
            if (tid < k) s_red[tid] += s_red[tid + k];
            __syncthreads();
        }
        if (tid == 0) {
            out[(size_t)T_TOK * E_DIM] = 1.25f * s_red[0] / (float)(T_TOK * E_DIM);
            g_done = 0;
        }
    }
}

extern "C" void kernel_launch(void* const* d_in, const int* in_sizes, int n_in,
                              void* d_out, int out_size) {
    const float* z   = (const float*)d_in[0];
    const float* emb = (const float*)d_in[1];
    float* out = (float*)d_out;

    cudaFuncSetAttribute(vq_main_kernel, cudaFuncAttributeMaxDynamicSharedMemorySize, SMEM_TOTAL);

    prep_kernel<<<N_E / 8, 256>>>(emb);
    vq_main_kernel<<<GRID_MAIN, 256, SMEM_TOTAL>>>(z, out);
}